// round 16
// baseline (speedup 1.0000x reference)
#include <cuda_runtime.h>
#include <cuda_fp16.h>
#include <math.h>
#include <stdint.h>

// Problem constants
#define Bsz 64
#define Nseq 197
#define Dm 768
#define NHd 8
#define HIDm 3072
#define BNROWS (Bsz * Nseq)          // 12608
#define LN_EPS 1e-5f
#define GEMM_GRID 296                // 2 CTAs x 148 SMs -> single wave

// ---------------- scratch (static device arrays; no allocations) ----------------
__device__ __align__(256) float g_P   [BNROWS * Dm];
__device__ __align__(256) float g_XP  [BNROWS * Dm];
__device__ __align__(256) float g_XRES[BNROWS * Dm];
__device__ __align__(256) float g_E1  [BNROWS];
// fp16 activation buffers
__device__ __align__(256) __half g_X1h [BNROWS * Dm];
__device__ __align__(256) __half g_QKVh[BNROWS * 3 * Dm];
__device__ __align__(256) __half g_CTXh[BNROWS * Dm];
__device__ __align__(256) __half g_Ph  [BNROWS * Dm];
__device__ __align__(256) __half g_X2h [BNROWS * Dm];
__device__ __align__(256) __half g_H1h [BNROWS * HIDm];
__device__ __align__(256) __half g_H2h [BNROWS * HIDm];
__device__ __align__(256) __half g_H3h [BNROWS * HIDm];
// fp16 weights
__device__ __align__(256) __half g_WQKVh [3 * Dm * Dm];
__device__ __align__(256) __half g_WPROJh[Dm * Dm];
__device__ __align__(256) __half g_WOAh  [Dm * Dm];
__device__ __align__(256) __half g_WOMh  [HIDm * HIDm];
__device__ __align__(256) __half g_WF1h  [HIDm * Dm];
__device__ __align__(256) __half g_WF2h  [Dm * HIDm];

// ---------------- helpers ----------------
__device__ __forceinline__ uint32_t smem_u32(const void* p) {
    uint32_t a;
    asm("{ .reg .u64 t; cvta.to.shared.u64 t, %1; cvt.u32.u64 %0, t; }" : "=r"(a) : "l"(p));
    return a;
}
__device__ __forceinline__ void ldsm_x4(uint32_t* r, uint32_t addr) {
    asm volatile("ldmatrix.sync.aligned.m8n8.x4.shared.b16 {%0,%1,%2,%3}, [%4];"
        : "=r"(r[0]), "=r"(r[1]), "=r"(r[2]), "=r"(r[3]) : "r"(addr));
}
__device__ __forceinline__ void ldsm_x4_t(uint32_t* r, uint32_t addr) {
    asm volatile("ldmatrix.sync.aligned.m8n8.x4.trans.shared.b16 {%0,%1,%2,%3}, [%4];"
        : "=r"(r[0]), "=r"(r[1]), "=r"(r[2]), "=r"(r[3]) : "r"(addr));
}
__device__ __forceinline__ void mma_f16(float* d, const uint32_t* a, uint32_t b0, uint32_t b1) {
    asm volatile("mma.sync.aligned.m16n8k16.row.col.f32.f16.f16.f32 "
        "{%0,%1,%2,%3}, {%4,%5,%6,%7}, {%8,%9}, {%0,%1,%2,%3};"
        : "+f"(d[0]), "+f"(d[1]), "+f"(d[2]), "+f"(d[3])
        : "r"(a[0]), "r"(a[1]), "r"(a[2]), "r"(a[3]), "r"(b0), "r"(b1));
}
__device__ __forceinline__ void cp_async16(uint32_t dst, const void* src, int src_bytes) {
    asm volatile("cp.async.cg.shared.global [%0], [%1], 16, %2;"
                 :: "r"(dst), "l"(src), "r"(src_bytes));
}
#define CP_COMMIT() asm volatile("cp.async.commit_group;" ::: "memory")
#define CP_WAIT1()  asm volatile("cp.async.wait_group 1;" ::: "memory")

__device__ __forceinline__ float warp_sum(float v) {
    #pragma unroll
    for (int o = 16; o; o >>= 1) v += __shfl_xor_sync(0xffffffffu, v, o);
    return v;
}
__device__ __forceinline__ float gelu_exact(float v) {
    return v * 0.5f * (1.0f + erff(v * 0.7071067811865476f));
}

// ---------------- merged weight prepass ----------------
#define SZ_QKV (3 * Dm * Dm)
#define SZ_PRJ (Dm * Dm)
#define SZ_OM  (HIDm * HIDm)
#define SZ_F1  (HIDm * Dm)
#define CUM0 SZ_QKV
#define CUM1 (CUM0 + SZ_PRJ)
#define CUM2 (CUM1 + SZ_PRJ)
#define CUM3 (CUM2 + SZ_OM)
#define CUM4 (CUM3 + SZ_F1)
#define CUM5 (CUM4 + SZ_F1)
__global__ __launch_bounds__(256) void prep_all(
    const float* __restrict__ qkv_w, const float* __restrict__ proj_w,
    const float* __restrict__ orth_a, const float* __restrict__ orth_m,
    const float* __restrict__ fc1_w, const float* __restrict__ fc2_w)
{
    int i = ((int)blockIdx.x * 256 + (int)threadIdx.x) * 4;
    if (i >= CUM5) return;
    const float* src; __half* dst; int off;
    if (i < CUM0)      { src = qkv_w;  dst = g_WQKVh;  off = i; }
    else if (i < CUM1) { src = proj_w; dst = g_WPROJh; off = i - CUM0; }
    else if (i < CUM2) { src = orth_a; dst = g_WOAh;   off = i - CUM1; }
    else if (i < CUM3) { src = orth_m; dst = g_WOMh;   off = i - CUM2; }
    else if (i < CUM4) { src = fc1_w;  dst = g_WF1h;   off = i - CUM3; }
    else               { src = fc2_w;  dst = g_WF2h;   off = i - CUM4; }
    float4 v = *(const float4*)(src + off);
    *(__half2*)(dst + off)     = __floats2half2_rn(v.x, v.y);
    *(__half2*)(dst + off + 2) = __floats2half2_rn(v.z, v.w);
}

// ---- persistent fp16 mma.sync GEMM with CONTINUOUS cross-tile cp.async stream ----
// 128 thr, 4 warps of 64x64, BK=64, 3-stage ring never drains between tiles.
#define STAGES 3
#define STAGE_BYTES 32768
#define GEMM_SMEM_BYTES (STAGES * STAGE_BYTES)   // 98304

__global__ void __launch_bounds__(128, 2) gemm_tc(
    const __half* __restrict__ A, const __half* __restrict__ W,
    const float* __restrict__ bias,
    float* __restrict__ C32, __half* __restrict__ C16,
    const float* __restrict__ add,
    int M, int Nn, int K, int do_gelu, int numTilesX, int numTiles)
{
    extern __shared__ char smc[];
    const uint32_t smb = smem_u32(smc);

    int tid = threadIdx.x;
    int wid = tid >> 5, lane = tid & 31;
    int gid = lane >> 2, tig = lane & 3;
    int lane16 = lane & 15, khalf = lane >> 4;
    int wm = (wid & 1) * 64;
    int wn = (wid >> 1) * 64;

    int cprow[8], cpc[8];
    uint32_t cpsw[8];
    #pragma unroll
    for (int l = 0; l < 8; l++) {
        int f = tid + l * 128;
        cprow[l] = f >> 3;
        cpc[l] = f & 7;
        cpsw[l] = ((uint32_t)cprow[l] << 7) | ((uint32_t)((cpc[l] ^ (cprow[l] & 7)) << 4));
    }
    uint32_t rx = (uint32_t)(lane16 & 7);
    uint32_t aoff[4], boff[4];
    #pragma unroll
    for (int mt = 0; mt < 4; mt++) aoff[mt] = (uint32_t)((wm + mt * 16 + lane16) << 7);
    #pragma unroll
    for (int p = 0; p < 4; p++) boff[p] = 16384u + (uint32_t)((wn + p * 16 + lane16) << 7);

    const int NC = K >> 6;
    if ((int)blockIdx.x >= numTiles) return;

    // prefetch cursor: next chunk to issue = (tile tp, k-chunk jp)
    int tp = blockIdx.x, jp = 0;
    int bmp = (tp / numTilesX) * 128, bnp = (tp % numTilesX) * 128;

    auto issueNext = [&](uint32_t sbase) {
        if (tp < numTiles) {
            int k0 = jp << 6;
            #pragma unroll
            for (int l = 0; l < 8; l++) {
                int gr = bmp + cprow[l];
                const __half* ga = A + (size_t)(gr < M ? gr : 0) * K + k0 + cpc[l] * 8;
                cp_async16(sbase + cpsw[l], ga, gr < M ? 16 : 0);
                const __half* gw = W + (size_t)(bnp + cprow[l]) * K + k0 + cpc[l] * 8;
                cp_async16(sbase + 16384u + cpsw[l], gw, 16);
            }
            if (++jp == NC) {
                jp = 0; tp += gridDim.x;
                if (tp < numTiles) {
                    bmp = (tp / numTilesX) * 128;
                    bnp = (tp % numTilesX) * 128;
                }
            }
        }
    };

    issueNext(smb); CP_COMMIT();
    issueNext(smb + STAGE_BYTES); CP_COMMIT();

    int stage = 0;
    for (int t = blockIdx.x; t < numTiles; t += gridDim.x) {
        int bm = (t / numTilesX) * 128;
        int bn = (t % numTilesX) * 128;

        float acc[4][8][4];
        #pragma unroll
        for (int mt = 0; mt < 4; mt++)
            #pragma unroll
            for (int nt = 0; nt < 8; nt++)
                #pragma unroll
                for (int r = 0; r < 4; r++) acc[mt][nt][r] = 0.f;

        for (int c = 0; c < NC; c++) {
            CP_WAIT1();
            __syncthreads();
            int s2 = stage + 2; if (s2 >= STAGES) s2 -= STAGES;
            issueNext(smb + s2 * STAGE_BYTES);
            CP_COMMIT();

            const uint32_t stb = smb + stage * STAGE_BYTES;
            #pragma unroll
            for (int kk = 0; kk < 4; kk++) {
                uint32_t kb = (uint32_t)(((((kk << 1) | khalf)) ^ rx) << 4);
                uint32_t af[4][4], bf[4][4];
                #pragma unroll
                for (int mt = 0; mt < 4; mt++) ldsm_x4(af[mt], stb + aoff[mt] + kb);
                #pragma unroll
                for (int p = 0; p < 4; p++) ldsm_x4(bf[p], stb + boff[p] + kb);
                #pragma unroll
                for (int mt = 0; mt < 4; mt++) {
                    #pragma unroll
                    for (int nt = 0; nt < 8; nt++) {
                        int p = nt >> 1, s = nt & 1;
                        mma_f16(acc[mt][nt], af[mt], bf[p][s], bf[p][2 + s]);
                    }
                }
            }
            stage = (stage + 1 == STAGES) ? 0 : stage + 1;
        }

        // epilogue (registers + gmem only; no smem -> no extra sync needed)
        #pragma unroll
        for (int mt = 0; mt < 4; mt++) {
            int row0 = bm + wm + mt * 16 + gid;
            #pragma unroll
            for (int half_ = 0; half_ < 2; half_++) {
                int row = row0 + half_ * 8;
                if (row >= M) continue;
                #pragma unroll
                for (int nt = 0; nt < 8; nt++) {
                    int col = bn + wn + nt * 8 + tig * 2;
                    float2 o;
                    o.x = acc[mt][nt][half_ * 2 + 0] + bias[col];
                    o.y = acc[mt][nt][half_ * 2 + 1] + bias[col + 1];
                    if (do_gelu) { o.x = gelu_exact(o.x); o.y = gelu_exact(o.y); }
                    if (add) {
                        const float2 a2 = *(const float2*)(add + (size_t)row * Nn + col);
                        o.x += a2.x; o.y += a2.y;
                    }
                    if (C32) *(float2*)(C32 + (size_t)row * Nn + col) = o;
                    if (C16) *(__half2*)(C16 + (size_t)row * Nn + col) = __floats2half2_rn(o.x, o.y);
                }
            }
        }
    }
}

// ---------------- LayerNorm -> fp16 out ----------------
__global__ __launch_bounds__(256) void ln16_kernel(
    const float* __restrict__ X, const float* __restrict__ gg, const float* __restrict__ bb,
    __half* __restrict__ out, int Dg)
{
    size_t row = blockIdx.x;
    const float* x = X + row * (size_t)Dg;
    float s = 0.f, s2 = 0.f;
    for (int i = threadIdx.x; i < Dg; i += 256) {
        float v = x[i];
        s += v; s2 += v * v;
    }
    __shared__ float sh0[8], sh1[8];
    s = warp_sum(s); s2 = warp_sum(s2);
    int w = threadIdx.x >> 5, lane = threadIdx.x & 31;
    if (lane == 0) { sh0[w] = s; sh1[w] = s2; }
    __syncthreads();
    float ts = 0.f, ts2 = 0.f;
    #pragma unroll
    for (int i = 0; i < 8; i++) { ts += sh0[i]; ts2 += sh1[i]; }
    float invD = 1.0f / (float)Dg;
    float mean = ts * invD;
    float rstd = rsqrtf(ts2 * invD - mean * mean + LN_EPS);
    for (int i = threadIdx.x; i < Dg; i += 256)
        out[row * (size_t)Dg + i] = __float2half((x[i] - mean) * rstd * gg[i] + bb[i]);
}

// ---------------- mma flash attention: one block (256 thr) per (b, h) ----------------
#define HD 96
#define KVROWS 208
#define KVSTR 104
#define ATTN_SMEM (2 * KVROWS * KVSTR * 2)   // 86528 B
__global__ void __launch_bounds__(256) attn_kernel(
    const __half* __restrict__ QKV, __half* __restrict__ CTX)
{
    extern __shared__ __half sha[];
    __half* Ksm = sha;
    __half* Vsm = sha + KVROWS * KVSTR;

    int bh = blockIdx.x;
    int b = bh / NHd, h = bh % NHd;
    int tid = threadIdx.x, lane = tid & 31, wid = tid >> 5;
    int gid = lane >> 2, tig = lane & 3;

    for (int idx = tid; idx < Nseq * 48; idx += 256) {
        int r = idx / 48, c = idx - r * 48;
        size_t g = (size_t)(b * Nseq + r) * (3 * Dm) + h * HD + 2 * c;
        *(uint32_t*)&Ksm[r * KVSTR + 2 * c] = *(const uint32_t*)&QKV[g + Dm];
        *(uint32_t*)&Vsm[r * KVSTR + 2 * c] = *(const uint32_t*)&QKV[g + 2 * Dm];
    }
    for (int idx = tid; idx < (KVROWS - Nseq) * 48; idx += 256) {
        int r = Nseq + idx / 48, c = idx % 48;
        *(uint32_t*)&Ksm[r * KVSTR + 2 * c] = 0;
        *(uint32_t*)&Vsm[r * KVSTR + 2 * c] = 0;
    }
    __syncthreads();

    const uint32_t kbase = smem_u32(Ksm), vbase = smem_u32(Vsm);
    const float scl = rsqrtf((float)HD);

    for (int mt = wid; mt < 13; mt += 8) {
        int bmrow = mt * 16;
        int r0 = bmrow + gid;     if (r0 > Nseq - 1) r0 = Nseq - 1;
        int r1 = bmrow + 8 + gid; if (r1 > Nseq - 1) r1 = Nseq - 1;
        size_t ro0 = (size_t)(b * Nseq + r0) * (3 * Dm) + h * HD;
        size_t ro1 = (size_t)(b * Nseq + r1) * (3 * Dm) + h * HD;
        uint32_t aq[6][4];
        #pragma unroll
        for (int kc = 0; kc < 6; kc++) {
            int c0 = kc * 16 + 2 * tig;
            aq[kc][0] = *(const uint32_t*)&QKV[ro0 + c0];
            aq[kc][1] = *(const uint32_t*)&QKV[ro1 + c0];
            aq[kc][2] = *(const uint32_t*)&QKV[ro0 + c0 + 8];
            aq[kc][3] = *(const uint32_t*)&QKV[ro1 + c0 + 8];
        }

        float sacc[25][4];
        #pragma unroll
        for (int jn = 0; jn < 25; jn++)
            #pragma unroll
            for (int r = 0; r < 4; r++) sacc[jn][r] = 0.f;

        int q4 = lane >> 3;
        #pragma unroll
        for (int jn = 0; jn < 25; jn++) {
            #pragma unroll
            for (int kk = 0; kk < 3; kk++) {
                uint32_t addr = kbase +
                    (uint32_t)(((jn * 8 + (lane & 7)) * KVSTR + kk * 32 + q4 * 8) * 2);
                uint32_t bf[4];
                ldsm_x4(bf, addr);
                mma_f16(sacc[jn], aq[2 * kk],     bf[0], bf[1]);
                mma_f16(sacc[jn], aq[2 * kk + 1], bf[2], bf[3]);
            }
        }

        float m0 = -1e30f, m1 = -1e30f;
        #pragma unroll
        for (int jn = 0; jn < 25; jn++) {
            int j0 = jn * 8 + 2 * tig;
            sacc[jn][0] = (j0     < Nseq) ? sacc[jn][0] * scl : -1e30f;
            sacc[jn][1] = (j0 + 1 < Nseq) ? sacc[jn][1] * scl : -1e30f;
            sacc[jn][2] = (j0     < Nseq) ? sacc[jn][2] * scl : -1e30f;
            sacc[jn][3] = (j0 + 1 < Nseq) ? sacc[jn][3] * scl : -1e30f;
            m0 = fmaxf(m0, fmaxf(sacc[jn][0], sacc[jn][1]));
            m1 = fmaxf(m1, fmaxf(sacc[jn][2], sacc[jn][3]));
        }
        m0 = fmaxf(m0, __shfl_xor_sync(0xffffffffu, m0, 1));
        m0 = fmaxf(m0, __shfl_xor_sync(0xffffffffu, m0, 2));
        m1 = fmaxf(m1, __shfl_xor_sync(0xffffffffu, m1, 1));
        m1 = fmaxf(m1, __shfl_xor_sync(0xffffffffu, m1, 2));
        float s0 = 0.f, s1 = 0.f;
        #pragma unroll
        for (int jn = 0; jn < 25; jn++) {
            sacc[jn][0] = __expf(sacc[jn][0] - m0);
            sacc[jn][1] = __expf(sacc[jn][1] - m0);
            sacc[jn][2] = __expf(sacc[jn][2] - m1);
            sacc[jn][3] = __expf(sacc[jn][3] - m1);
            s0 += sacc[jn][0] + sacc[jn][1];
            s1 += sacc[jn][2] + sacc[jn][3];
        }
        s0 += __shfl_xor_sync(0xffffffffu, s0, 1);
        s0 += __shfl_xor_sync(0xffffffffu, s0, 2);
        s1 += __shfl_xor_sync(0xffffffffu, s1, 1);
        s1 += __shfl_xor_sync(0xffffffffu, s1, 2);
        float inv0 = 1.0f / s0, inv1 = 1.0f / s1;

        float oacc[12][4];
        #pragma unroll
        for (int dn = 0; dn < 12; dn++)
            #pragma unroll
            for (int r = 0; r < 4; r++) oacc[dn][r] = 0.f;

        #pragma unroll
        for (int kc2 = 0; kc2 < 13; kc2++) {
            int jn0 = 2 * kc2, jn1 = 2 * kc2 + 1;
            uint32_t p0, p1, p2, p3;
            {
                __half2 t0 = __floats2half2_rn(sacc[jn0][0], sacc[jn0][1]);
                __half2 t1 = __floats2half2_rn(sacc[jn0][2], sacc[jn0][3]);
                p0 = *(uint32_t*)&t0; p1 = *(uint32_t*)&t1;
            }
            if (jn1 < 25) {
                __half2 t2 = __floats2half2_rn(sacc[jn1][0], sacc[jn1][1]);
                __half2 t3 = __floats2half2_rn(sacc[jn1][2], sacc[jn1][3]);
                p2 = *(uint32_t*)&t2; p3 = *(uint32_t*)&t3;
            } else { p2 = 0u; p3 = 0u; }
            uint32_t pfrag[4] = { p0, p1, p2, p3 };

            #pragma unroll
            for (int dn = 0; dn < 12; dn += 2) {
                uint32_t addr = vbase +
                    (uint32_t)(((kc2 * 16 + (q4 & 1) * 8 + (lane & 7)) * KVSTR
                                + dn * 8 + (q4 >> 1) * 8) * 2);
                uint32_t bv[4];
                ldsm_x4_t(bv, addr);
                mma_f16(oacc[dn],     pfrag, bv[0], bv[1]);
                mma_f16(oacc[dn + 1], pfrag, bv[2], bv[3]);
            }
        }

        int row0 = bmrow + gid, row1 = bmrow + 8 + gid;
        #pragma unroll
        for (int dn = 0; dn < 12; dn++) {
            int d = dn * 8 + 2 * tig;
            if (row0 < Nseq)
                *(__half2*)&CTX[(size_t)(b * Nseq + row0) * Dm + h * HD + d] =
                    __floats2half2_rn(oacc[dn][0] * inv0, oacc[dn][1] * inv0);
            if (row1 < Nseq)
                *(__half2*)&CTX[(size_t)(b * Nseq + row1) * Dm + h * HD + d] =
                    __floats2half2_rn(oacc[dn][2] * inv1, oacc[dn][3] * inv1);
        }
    }
}

// ---------------- adapter A: so8 + LN_a + residual + fused LN2 -> fp16 ----------------
__global__ __launch_bounds__(256) void so8ln_a_kernel(
    const float* __restrict__ XP, const float* __restrict__ P, const float* __restrict__ xin,
    const float* __restrict__ eps, const float* __restrict__ scale_p,
    const float* __restrict__ g1, const float* __restrict__ b1,
    const float* __restrict__ g2, const float* __restrict__ b2,
    float* __restrict__ XRES, __half* __restrict__ X2h, float* __restrict__ err)
{
    __shared__ float y[Dm];
    __shared__ float errsum[8];
    __shared__ float sh0[8], sh1[8];
    size_t row = blockIdx.x;
    int tid = threadIdx.x;
    const int hd = Dm / 8;
    if (tid < 8) errsum[tid] = 0.f;
    __syncthreads();
    float scale = scale_p[0];
    const float* xp = XP + row * (size_t)Dm;
    const float* bs = P + row * (size_t)Dm;

    float s = 0.f, s2 = 0.f;
    for (int i = tid; i < Dm; i += 256) {
        int head = i / hd;
        int pos = i - head * hd;
        float v;
        if (pos < 8) {
            int pr = pos >> 1;
            float ang = eps[row * 32 + head * 4 + pr] * scale;
            float sn, c;
            sincosf(ang, &sn, &c);
            float e = xp[head * hd + 2 * pr];
            float o = xp[head * hd + 2 * pr + 1];
            float rot, orig;
            if (pos & 1) { rot = e * sn + o * c; orig = o; }
            else         { rot = e * c - o * sn; orig = e; }
            float d = rot - orig;
            atomicAdd(&errsum[head], d * d);
            v = rot;
        } else v = xp[i];
        v += bs[i];
        y[i] = v;
        s += v; s2 += v * v;
    }
    s = warp_sum(s); s2 = warp_sum(s2);
    int w = tid >> 5, lane = tid & 31;
    if (lane == 0) { sh0[w] = s; sh1[w] = s2; }
    __syncthreads();
    float ts = 0.f, ts2 = 0.f;
    #pragma unroll
    for (int i = 0; i < 8; i++) { ts += sh0[i]; ts2 += sh1[i]; }
    if (tid == 0) {
        float e = 0.f;
        #pragma unroll
        for (int hh = 0; hh < 8; hh++) e += sqrtf(errsum[hh]);
        err[row] = e * 0.125f;
    }
    const float invD = 1.0f / (float)Dm;
    float mean = ts * invD;
    float rstd = rsqrtf(ts2 * invD - mean * mean + LN_EPS);
    __syncthreads();

    s = 0.f; s2 = 0.f;
    for (int i = tid; i < Dm; i += 256) {
        float v = (y[i] - mean) * rstd * g1[i] + b1[i] + bs[i] + xin[row * (size_t)Dm + i];
        XRES[row * (size_t)Dm + i] = v;
        y[i] = v;
        s += v; s2 += v * v;
    }
    s = warp_sum(s); s2 = warp_sum(s2);
    if (lane == 0) { sh0[w] = s; sh1[w] = s2; }
    __syncthreads();
    ts = 0.f; ts2 = 0.f;
    #pragma unroll
    for (int i = 0; i < 8; i++) { ts += sh0[i]; ts2 += sh1[i]; }
    float mean2 = ts * invD;
    float rstd2 = rsqrtf(ts2 * invD - mean2 * mean2 + LN_EPS);
    for (int i = tid; i < Dm; i += 256)
        X2h[row * (size_t)Dm + i] = __float2half((y[i] - mean2) * rstd2 * g2[i] + b2[i]);
}

// ---------------- adapter M: so8 + LN_m + residual -> fp16 ; err tail ----------------
__global__ __launch_bounds__(256) void so8ln_m_kernel(
    const __half* __restrict__ H2h, const __half* __restrict__ H1h,
    const float* __restrict__ eps, const float* __restrict__ scale_p,
    const float* __restrict__ gg, const float* __restrict__ bb,
    const float* __restrict__ e1, float* __restrict__ out_tail,
    __half* __restrict__ H3h)
{
    __shared__ float y[HIDm];
    __shared__ float errsum[8];
    __shared__ float sh0[8], sh1[8];
    size_t row = blockIdx.x;
    int tid = threadIdx.x;
    const int hd = HIDm / 8;
    if (tid < 8) errsum[tid] = 0.f;
    __syncthreads();
    float scale = scale_p[0];
    const __half* xph = H2h + row * (size_t)HIDm;
    const __half* bsh = H1h + row * (size_t)HIDm;

    float s = 0.f, s2 = 0.f;
    for (int i = tid; i < HIDm; i += 256) {
        int head = i / hd;
        int pos = i - head * hd;
        float v;
        if (pos < 8) {
            int pr = pos >> 1;
            float ang = eps[row * 32 + head * 4 + pr] * scale;
            float sn, c;
            sincosf(ang, &sn, &c);
            float e = __half2float(xph[head * hd + 2 * pr]);
            float o = __half2float(xph[head * hd + 2 * pr + 1]);
            float rot, orig;
            if (pos & 1) { rot = e * sn + o * c; orig = o; }
            else         { rot = e * c - o * sn; orig = e; }
            float d = rot - orig;
            atomicAdd(&errsum[head], d * d);
            v = rot;
        } else v = __half2float(xph[i]);
        v += __half2float(bsh[i]);
        y[i] = v;
        s += v; s2 += v * v;
    }
    s = warp_sum(s); s2 = warp_sum(s2);
    int w = tid >> 5, lane = tid & 31;
    if (lane == 0) { sh0[w] = s; sh1[w] = s2; }
    __syncthreads();
    float ts = 0.f, ts2 = 0.f;
    #pragma unroll
    for (int i = 0; i < 8; i++) { ts += sh0[i]; ts2 += sh1[i]; }
    if (tid == 0) {
        float e = 0.f;
        #pragma unroll
        for (int hh = 0; hh < 8; hh++) e += sqrtf(errsum[hh]);
        out_tail[row] = e * 0.125f + e1[row];
    }
    const float invD = 1.0f / (float)HIDm;
    float mean = ts * invD;
    float rstd = rsqrtf(ts2 * invD - mean * mean + LN_EPS);
    for (int i = tid; i < HIDm; i += 256)
        H3h[row * (size_t)HIDm + i] =
            __float2half((y[i] - mean) * rstd * gg[i] + bb[i] + __half2float(bsh[i]));
}

// ---------------- launch ----------------
extern "C" void kernel_launch(void* const* d_in, const int* in_sizes, int n_in,
                              void* d_out, int out_size)
{
    const float* x       = (const float*)d_in[0];
    const float* qkv_w   = (const float*)d_in[1];
    const float* qkv_b   = (const float*)d_in[2];
    const float* proj_w  = (const float*)d_in[3];
    const float* proj_b  = (const float*)d_in[4];
    const float* norm1_g = (const float*)d_in[5];
    const float* norm1_b = (const float*)d_in[6];
    const float* norm2_g = (const float*)d_in[7];
    const float* norm2_b = (const float*)d_in[8];
    const float* orth_w_a = (const float*)d_in[9];
    const float* orth_b_a = (const float*)d_in[10];
    const float* scale_a  = (const float*)d_in[11];
    const float* ln_g_a   = (const float*)d_in[12];
    const float* ln_b_a   = (const float*)d_in[13];
    const float* orth_w_m = (const float*)d_in[14];
    const float* orth_b_m = (const float*)d_in[15];
    const float* scale_m  = (const float*)d_in[16];
    const float* ln_g_m   = (const float*)d_in[17];
    const float* ln_b_m   = (const float*)d_in[18];
    const float* fc1_w    = (const float*)d_in[19];
    const float* fc1_b    = (const float*)d_in[20];
    const float* fc2_w    = (const float*)d_in[21];
    const float* fc2_b    = (const float*)d_in[22];
    const float* eps_a    = (const float*)d_in[23];
    const float* eps_m    = (const float*)d_in[24];
    float* out = (float*)d_out;

    float *P, *XP, *XRES, *E1;
    __half *X1h, *QKVh, *CTXh, *Ph, *X2h, *H1h, *H2h, *H3h;
    __half *WQKVh, *WPROJh, *WOAh, *WOMh, *WF1h, *WF2h;
    cudaGetSymbolAddress((void**)&P,    g_P);
    cudaGetSymbolAddress((void**)&XP,   g_XP);
    cudaGetSymbolAddress((void**)&XRES, g_XRES);
    cudaGetSymbolAddress((void**)&E1,   g_E1);
    cudaGetSymbolAddress((void**)&X1h,  g_X1h);
    cudaGetSymbolAddress((void**)&QKVh, g_QKVh);
    cudaGetSymbolAddress((void**)&CTXh, g_CTXh);
    cudaGetSymbolAddress((void**)&Ph,   g_Ph);
    cudaGetSymbolAddress((void**)&X2h,  g_X2h);
    cudaGetSymbolAddress((void**)&H1h,  g_H1h);
    cudaGetSymbolAddress((void**)&H2h,  g_H2h);
    cudaGetSymbolAddress((void**)&H3h,  g_H3h);
    cudaGetSymbolAddress((void**)&WQKVh,  g_WQKVh);
    cudaGetSymbolAddress((void**)&WPROJh, g_WPROJh);
    cudaGetSymbolAddress((void**)&WOAh,   g_WOAh);
    cudaGetSymbolAddress((void**)&WOMh,   g_WOMh);
    cudaGetSymbolAddress((void**)&WF1h,   g_WF1h);
    cudaGetSymbolAddress((void**)&WF2h,   g_WF2h);

    cudaFuncSetAttribute(attn_kernel, cudaFuncAttributeMaxDynamicSharedMemorySize, ATTN_SMEM);
    cudaFuncSetAttribute(gemm_tc, cudaFuncAttributeMaxDynamicSharedMemorySize, GEMM_SMEM_BYTES);

    const int MROWS = BNROWS;
    const int GY = (MROWS + 127) / 128;    // 99
    dim3 blk256(256);
    dim3 blk128(128);

    auto gemm = [&](const __half* A, const __half* W, const float* bias,
                    float* C32, __half* C16, const float* add,
                    int Nn, int K, int do_gelu) {
        int ntx = Nn / 128;
        int nt = ntx * GY;
        int grid = nt < GEMM_GRID ? nt : GEMM_GRID;
        gemm_tc<<<grid, blk128, GEMM_SMEM_BYTES>>>(
            A, W, bias, C32, C16, add, MROWS, Nn, K, do_gelu, ntx, nt);
    };

    // 1) merged fp16 weight prepass
    prep_all<<<(CUM5 / 4 + 255) / 256, blk256>>>(qkv_w, proj_w, orth_w_a, orth_w_m, fc1_w, fc2_w);
    // 2) x1h = fp16(LN1(x))
    ln16_kernel<<<MROWS, blk256>>>(x, norm1_g, norm1_b, X1h, Dm);
    // 3) qkvh = x1 @ qkv_w^T + qkv_b
    gemm(X1h, WQKVh, qkv_b, nullptr, QKVh, nullptr, 3 * Dm, Dm, 0);
    // 4) attention (mma) -> ctxh
    attn_kernel<<<Bsz * NHd, blk256, ATTN_SMEM>>>(QKVh, CTXh);
    // 5) proj -> P (fp32) + Ph (fp16)
    gemm(CTXh, WPROJh, proj_b, P, Ph, nullptr, Dm, Dm, 0);
    // 6) xp = P @ orth_w_a^T + b
    gemm(Ph, WOAh, orth_b_a, XP, nullptr, nullptr, Dm, Dm, 0);
    // 7) adapter A fused
    so8ln_a_kernel<<<MROWS, blk256>>>(XP, P, x, eps_a, scale_a,
                                      ln_g_a, ln_b_a, norm2_g, norm2_b, XRES, X2h, E1);
    // 8) h1 = gelu(x2 @ fc1^T + b) -> H1h
    gemm(X2h, WF1h, fc1_b, nullptr, H1h, nullptr, HIDm, Dm, 1);
    // 9) h2 = h1 @ orth_w_m^T + b -> H2h (fp16 only)
    gemm(H1h, WOMh, orth_b_m, nullptr, H2h, nullptr, HIDm, HIDm, 0);
    // 10) adapter M fused
    so8ln_m_kernel<<<MROWS, blk256>>>(H2h, H1h, eps_m, scale_m, ln_g_m, ln_b_m,
                                      E1, out + (size_t)MROWS * Dm, H3h);
    // 11) out = h3 @ fc2^T + b + xres
    gemm(H3h, WF2h, fc2_b, out, nullptr, XRES, Dm, HIDm, 0);
}

// round 17
// speedup vs baseline: 1.1765x; 1.1765x over previous
#include <cuda_runtime.h>
#include <cuda_fp16.h>
#include <math.h>
#include <stdint.h>

// Problem constants
#define Bsz 64
#define Nseq 197
#define Dm 768
#define NHd 8
#define HIDm 3072
#define BNROWS (Bsz * Nseq)          // 12608
#define LN_EPS 1e-5f

// ---------------- scratch (static device arrays; no allocations) ----------------
__device__ __align__(256) float g_XRES[BNROWS * Dm];
__device__ __align__(256) float g_E1  [BNROWS];
// fp16 activation buffers
__device__ __align__(256) __half g_X1h [BNROWS * Dm];   // LN1 out, later reused for XP
__device__ __align__(256) __half g_QKVh[BNROWS * 3 * Dm];
__device__ __align__(256) __half g_CTXh[BNROWS * Dm];
__device__ __align__(256) __half g_Ph  [BNROWS * Dm];
__device__ __align__(256) __half g_X2h [BNROWS * Dm];
__device__ __align__(256) __half g_H1h [BNROWS * HIDm];
__device__ __align__(256) __half g_H2h [BNROWS * HIDm];
__device__ __align__(256) __half g_H3h [BNROWS * HIDm];
// fp16 weights
__device__ __align__(256) __half g_WQKVh [3 * Dm * Dm];
__device__ __align__(256) __half g_WPROJh[Dm * Dm];
__device__ __align__(256) __half g_WOAh  [Dm * Dm];
__device__ __align__(256) __half g_WOMh  [HIDm * HIDm];
__device__ __align__(256) __half g_WF1h  [HIDm * Dm];
__device__ __align__(256) __half g_WF2h  [Dm * HIDm];

// ---------------- helpers ----------------
__device__ __forceinline__ uint32_t smem_u32(const void* p) {
    uint32_t a;
    asm("{ .reg .u64 t; cvta.to.shared.u64 t, %1; cvt.u32.u64 %0, t; }" : "=r"(a) : "l"(p));
    return a;
}
__device__ __forceinline__ void ldsm_x4(uint32_t* r, uint32_t addr) {
    asm volatile("ldmatrix.sync.aligned.m8n8.x4.shared.b16 {%0,%1,%2,%3}, [%4];"
        : "=r"(r[0]), "=r"(r[1]), "=r"(r[2]), "=r"(r[3]) : "r"(addr));
}
__device__ __forceinline__ void ldsm_x4_t(uint32_t* r, uint32_t addr) {
    asm volatile("ldmatrix.sync.aligned.m8n8.x4.trans.shared.b16 {%0,%1,%2,%3}, [%4];"
        : "=r"(r[0]), "=r"(r[1]), "=r"(r[2]), "=r"(r[3]) : "r"(addr));
}
__device__ __forceinline__ void mma_f16(float* d, const uint32_t* a, uint32_t b0, uint32_t b1) {
    asm volatile("mma.sync.aligned.m16n8k16.row.col.f32.f16.f16.f32 "
        "{%0,%1,%2,%3}, {%4,%5,%6,%7}, {%8,%9}, {%0,%1,%2,%3};"
        : "+f"(d[0]), "+f"(d[1]), "+f"(d[2]), "+f"(d[3])
        : "r"(a[0]), "r"(a[1]), "r"(a[2]), "r"(a[3]), "r"(b0), "r"(b1));
}
__device__ __forceinline__ void cp_async16(uint32_t dst, const void* src, int src_bytes) {
    asm volatile("cp.async.cg.shared.global [%0], [%1], 16, %2;"
                 :: "r"(dst), "l"(src), "r"(src_bytes));
}
#define CP_COMMIT() asm volatile("cp.async.commit_group;" ::: "memory")
#define CP_WAIT1()  asm volatile("cp.async.wait_group 1;" ::: "memory")

__device__ __forceinline__ float warp_sum(float v) {
    #pragma unroll
    for (int o = 16; o; o >>= 1) v += __shfl_xor_sync(0xffffffffu, v, o);
    return v;
}
__device__ __forceinline__ float gelu_exact(float v) {
    return v * 0.5f * (1.0f + erff(v * 0.7071067811865476f));
}

// ---------------- merged weight prepass ----------------
#define SZ_QKV (3 * Dm * Dm)
#define SZ_PRJ (Dm * Dm)
#define SZ_OM  (HIDm * HIDm)
#define SZ_F1  (HIDm * Dm)
#define CUM0 SZ_QKV
#define CUM1 (CUM0 + SZ_PRJ)
#define CUM2 (CUM1 + SZ_PRJ)
#define CUM3 (CUM2 + SZ_OM)
#define CUM4 (CUM3 + SZ_F1)
#define CUM5 (CUM4 + SZ_F1)
__global__ __launch_bounds__(256) void prep_all(
    const float* __restrict__ qkv_w, const float* __restrict__ proj_w,
    const float* __restrict__ orth_a, const float* __restrict__ orth_m,
    const float* __restrict__ fc1_w, const float* __restrict__ fc2_w)
{
    int i = ((int)blockIdx.x * 256 + (int)threadIdx.x) * 4;
    if (i >= CUM5) return;
    const float* src; __half* dst; int off;
    if (i < CUM0)      { src = qkv_w;  dst = g_WQKVh;  off = i; }
    else if (i < CUM1) { src = proj_w; dst = g_WPROJh; off = i - CUM0; }
    else if (i < CUM2) { src = orth_a; dst = g_WOAh;   off = i - CUM1; }
    else if (i < CUM3) { src = orth_m; dst = g_WOMh;   off = i - CUM2; }
    else if (i < CUM4) { src = fc1_w;  dst = g_WF1h;   off = i - CUM3; }
    else               { src = fc2_w;  dst = g_WF2h;   off = i - CUM4; }
    float4 v = *(const float4*)(src + off);
    *(__half2*)(dst + off)     = __floats2half2_rn(v.x, v.y);
    *(__half2*)(dst + off + 2) = __floats2half2_rn(v.z, v.w);
}

// ---------------- fp16 mma.sync GEMM: 128 thr, 4 warps of 64x64, BK=64 (R13 config) ----
#define STAGES 3
#define STAGE_BYTES 32768
#define GEMM_SMEM_BYTES (STAGES * STAGE_BYTES)   // 98304

__global__ void __launch_bounds__(128, 2) gemm_tc(
    const __half* __restrict__ A, const __half* __restrict__ W,
    const float* __restrict__ bias,
    float* __restrict__ C32, __half* __restrict__ C16,
    const float* __restrict__ add,
    int M, int Nn, int K, int do_gelu)
{
    extern __shared__ char smc[];
    const uint32_t smb = smem_u32(smc);

    int tid = threadIdx.x;
    int wid = tid >> 5, lane = tid & 31;
    int gid = lane >> 2, tig = lane & 3;
    int lane16 = lane & 15, khalf = lane >> 4;
    int wm = (wid & 1) * 64;
    int wn = (wid >> 1) * 64;
    int bm = blockIdx.y * 128, bn = blockIdx.x * 128;

    int cprow[8], cpc[8];
    uint32_t cpsw[8];
    #pragma unroll
    for (int l = 0; l < 8; l++) {
        int f = tid + l * 128;
        cprow[l] = f >> 3;
        cpc[l] = f & 7;
        cpsw[l] = ((uint32_t)cprow[l] << 7) | ((uint32_t)((cpc[l] ^ (cprow[l] & 7)) << 4));
    }
    uint32_t rx = (uint32_t)(lane16 & 7);
    uint32_t aoff[4], boff[4];
    #pragma unroll
    for (int mt = 0; mt < 4; mt++) aoff[mt] = (uint32_t)((wm + mt * 16 + lane16) << 7);
    #pragma unroll
    for (int p = 0; p < 4; p++) boff[p] = 16384u + (uint32_t)((wn + p * 16 + lane16) << 7);

    float acc[4][8][4];
    #pragma unroll
    for (int mt = 0; mt < 4; mt++)
        #pragma unroll
        for (int nt = 0; nt < 8; nt++)
            #pragma unroll
            for (int r = 0; r < 4; r++) acc[mt][nt][r] = 0.f;

    const int NC = K >> 6;

    auto issue = [&](int k0, uint32_t sbase) {
        #pragma unroll
        for (int l = 0; l < 8; l++) {
            int gr = bm + cprow[l];
            const __half* ga = A + (size_t)(gr < M ? gr : 0) * K + k0 + cpc[l] * 8;
            cp_async16(sbase + cpsw[l], ga, gr < M ? 16 : 0);
            const __half* gw = W + (size_t)(bn + cprow[l]) * K + k0 + cpc[l] * 8;
            cp_async16(sbase + 16384u + cpsw[l], gw, 16);
        }
    };

    issue(0, smb); CP_COMMIT();
    issue(64, smb + STAGE_BYTES); CP_COMMIT();

    int stage = 0;
    for (int c = 0; c < NC; c++) {
        CP_WAIT1();
        __syncthreads();
        int s2 = stage + 2; if (s2 >= STAGES) s2 -= STAGES;
        if (c + 2 < NC) issue((c + 2) << 6, smb + s2 * STAGE_BYTES);
        CP_COMMIT();

        const uint32_t stb = smb + stage * STAGE_BYTES;
        #pragma unroll
        for (int kk = 0; kk < 4; kk++) {
            uint32_t kb = (uint32_t)(((((kk << 1) | khalf)) ^ rx) << 4);
            uint32_t af[4][4], bf[4][4];
            #pragma unroll
            for (int mt = 0; mt < 4; mt++) ldsm_x4(af[mt], stb + aoff[mt] + kb);
            #pragma unroll
            for (int p = 0; p < 4; p++) ldsm_x4(bf[p], stb + boff[p] + kb);
            #pragma unroll
            for (int mt = 0; mt < 4; mt++) {
                #pragma unroll
                for (int nt = 0; nt < 8; nt++) {
                    int p = nt >> 1, s = nt & 1;
                    mma_f16(acc[mt][nt], af[mt], bf[p][s], bf[p][2 + s]);
                }
            }
        }
        stage = (stage + 1 == STAGES) ? 0 : stage + 1;
    }

    // epilogue
    #pragma unroll
    for (int mt = 0; mt < 4; mt++) {
        int row0 = bm + wm + mt * 16 + gid;
        #pragma unroll
        for (int half_ = 0; half_ < 2; half_++) {
            int row = row0 + half_ * 8;
            if (row >= M) continue;
            #pragma unroll
            for (int nt = 0; nt < 8; nt++) {
                int col = bn + wn + nt * 8 + tig * 2;
                float2 o;
                o.x = acc[mt][nt][half_ * 2 + 0] + bias[col];
                o.y = acc[mt][nt][half_ * 2 + 1] + bias[col + 1];
                if (do_gelu) { o.x = gelu_exact(o.x); o.y = gelu_exact(o.y); }
                if (add) {
                    const float2 a2 = *(const float2*)(add + (size_t)row * Nn + col);
                    o.x += a2.x; o.y += a2.y;
                }
                if (C32) *(float2*)(C32 + (size_t)row * Nn + col) = o;
                if (C16) *(__half2*)(C16 + (size_t)row * Nn + col) = __floats2half2_rn(o.x, o.y);
            }
        }
    }
}

// ---------------- LayerNorm -> fp16 out ----------------
__global__ __launch_bounds__(256) void ln16_kernel(
    const float* __restrict__ X, const float* __restrict__ gg, const float* __restrict__ bb,
    __half* __restrict__ out, int Dg)
{
    size_t row = blockIdx.x;
    const float* x = X + row * (size_t)Dg;
    float s = 0.f, s2 = 0.f;
    for (int i = threadIdx.x; i < Dg; i += 256) {
        float v = x[i];
        s += v; s2 += v * v;
    }
    __shared__ float sh0[8], sh1[8];
    s = warp_sum(s); s2 = warp_sum(s2);
    int w = threadIdx.x >> 5, lane = threadIdx.x & 31;
    if (lane == 0) { sh0[w] = s; sh1[w] = s2; }
    __syncthreads();
    float ts = 0.f, ts2 = 0.f;
    #pragma unroll
    for (int i = 0; i < 8; i++) { ts += sh0[i]; ts2 += sh1[i]; }
    float invD = 1.0f / (float)Dg;
    float mean = ts * invD;
    float rstd = rsqrtf(ts2 * invD - mean * mean + LN_EPS);
    for (int i = threadIdx.x; i < Dg; i += 256)
        out[row * (size_t)Dg + i] = __float2half((x[i] - mean) * rstd * gg[i] + bb[i]);
}

// ---------------- mma flash attention: one block (256 thr) per (b, h) ----------------
#define HD 96
#define KVROWS 208
#define KVSTR 104
#define ATTN_SMEM (2 * KVROWS * KVSTR * 2)   // 86528 B
__global__ void __launch_bounds__(256) attn_kernel(
    const __half* __restrict__ QKV, __half* __restrict__ CTX)
{
    extern __shared__ __half sha[];
    __half* Ksm = sha;
    __half* Vsm = sha + KVROWS * KVSTR;

    int bh = blockIdx.x;
    int b = bh / NHd, h = bh % NHd;
    int tid = threadIdx.x, lane = tid & 31, wid = tid >> 5;
    int gid = lane >> 2, tig = lane & 3;

    for (int idx = tid; idx < Nseq * 48; idx += 256) {
        int r = idx / 48, c = idx - r * 48;
        size_t g = (size_t)(b * Nseq + r) * (3 * Dm) + h * HD + 2 * c;
        *(uint32_t*)&Ksm[r * KVSTR + 2 * c] = *(const uint32_t*)&QKV[g + Dm];
        *(uint32_t*)&Vsm[r * KVSTR + 2 * c] = *(const uint32_t*)&QKV[g + 2 * Dm];
    }
    for (int idx = tid; idx < (KVROWS - Nseq) * 48; idx += 256) {
        int r = Nseq + idx / 48, c = idx % 48;
        *(uint32_t*)&Ksm[r * KVSTR + 2 * c] = 0;
        *(uint32_t*)&Vsm[r * KVSTR + 2 * c] = 0;
    }
    __syncthreads();

    const uint32_t kbase = smem_u32(Ksm), vbase = smem_u32(Vsm);
    const float scl = rsqrtf((float)HD);

    for (int mt = wid; mt < 13; mt += 8) {
        int bmrow = mt * 16;
        int r0 = bmrow + gid;     if (r0 > Nseq - 1) r0 = Nseq - 1;
        int r1 = bmrow + 8 + gid; if (r1 > Nseq - 1) r1 = Nseq - 1;
        size_t ro0 = (size_t)(b * Nseq + r0) * (3 * Dm) + h * HD;
        size_t ro1 = (size_t)(b * Nseq + r1) * (3 * Dm) + h * HD;
        uint32_t aq[6][4];
        #pragma unroll
        for (int kc = 0; kc < 6; kc++) {
            int c0 = kc * 16 + 2 * tig;
            aq[kc][0] = *(const uint32_t*)&QKV[ro0 + c0];
            aq[kc][1] = *(const uint32_t*)&QKV[ro1 + c0];
            aq[kc][2] = *(const uint32_t*)&QKV[ro0 + c0 + 8];
            aq[kc][3] = *(const uint32_t*)&QKV[ro1 + c0 + 8];
        }

        float sacc[25][4];
        #pragma unroll
        for (int jn = 0; jn < 25; jn++)
            #pragma unroll
            for (int r = 0; r < 4; r++) sacc[jn][r] = 0.f;

        int q4 = lane >> 3;
        #pragma unroll
        for (int jn = 0; jn < 25; jn++) {
            #pragma unroll
            for (int kk = 0; kk < 3; kk++) {
                uint32_t addr = kbase +
                    (uint32_t)(((jn * 8 + (lane & 7)) * KVSTR + kk * 32 + q4 * 8) * 2);
                uint32_t bf[4];
                ldsm_x4(bf, addr);
                mma_f16(sacc[jn], aq[2 * kk],     bf[0], bf[1]);
                mma_f16(sacc[jn], aq[2 * kk + 1], bf[2], bf[3]);
            }
        }

        float m0 = -1e30f, m1 = -1e30f;
        #pragma unroll
        for (int jn = 0; jn < 25; jn++) {
            int j0 = jn * 8 + 2 * tig;
            sacc[jn][0] = (j0     < Nseq) ? sacc[jn][0] * scl : -1e30f;
            sacc[jn][1] = (j0 + 1 < Nseq) ? sacc[jn][1] * scl : -1e30f;
            sacc[jn][2] = (j0     < Nseq) ? sacc[jn][2] * scl : -1e30f;
            sacc[jn][3] = (j0 + 1 < Nseq) ? sacc[jn][3] * scl : -1e30f;
            m0 = fmaxf(m0, fmaxf(sacc[jn][0], sacc[jn][1]));
            m1 = fmaxf(m1, fmaxf(sacc[jn][2], sacc[jn][3]));
        }
        m0 = fmaxf(m0, __shfl_xor_sync(0xffffffffu, m0, 1));
        m0 = fmaxf(m0, __shfl_xor_sync(0xffffffffu, m0, 2));
        m1 = fmaxf(m1, __shfl_xor_sync(0xffffffffu, m1, 1));
        m1 = fmaxf(m1, __shfl_xor_sync(0xffffffffu, m1, 2));
        float s0 = 0.f, s1 = 0.f;
        #pragma unroll
        for (int jn = 0; jn < 25; jn++) {
            sacc[jn][0] = __expf(sacc[jn][0] - m0);
            sacc[jn][1] = __expf(sacc[jn][1] - m0);
            sacc[jn][2] = __expf(sacc[jn][2] - m1);
            sacc[jn][3] = __expf(sacc[jn][3] - m1);
            s0 += sacc[jn][0] + sacc[jn][1];
            s1 += sacc[jn][2] + sacc[jn][3];
        }
        s0 += __shfl_xor_sync(0xffffffffu, s0, 1);
        s0 += __shfl_xor_sync(0xffffffffu, s0, 2);
        s1 += __shfl_xor_sync(0xffffffffu, s1, 1);
        s1 += __shfl_xor_sync(0xffffffffu, s1, 2);
        float inv0 = 1.0f / s0, inv1 = 1.0f / s1;

        float oacc[12][4];
        #pragma unroll
        for (int dn = 0; dn < 12; dn++)
            #pragma unroll
            for (int r = 0; r < 4; r++) oacc[dn][r] = 0.f;

        #pragma unroll
        for (int kc2 = 0; kc2 < 13; kc2++) {
            int jn0 = 2 * kc2, jn1 = 2 * kc2 + 1;
            uint32_t p0, p1, p2, p3;
            {
                __half2 t0 = __floats2half2_rn(sacc[jn0][0], sacc[jn0][1]);
                __half2 t1 = __floats2half2_rn(sacc[jn0][2], sacc[jn0][3]);
                p0 = *(uint32_t*)&t0; p1 = *(uint32_t*)&t1;
            }
            if (jn1 < 25) {
                __half2 t2 = __floats2half2_rn(sacc[jn1][0], sacc[jn1][1]);
                __half2 t3 = __floats2half2_rn(sacc[jn1][2], sacc[jn1][3]);
                p2 = *(uint32_t*)&t2; p3 = *(uint32_t*)&t3;
            } else { p2 = 0u; p3 = 0u; }
            uint32_t pfrag[4] = { p0, p1, p2, p3 };

            #pragma unroll
            for (int dn = 0; dn < 12; dn += 2) {
                uint32_t addr = vbase +
                    (uint32_t)(((kc2 * 16 + (q4 & 1) * 8 + (lane & 7)) * KVSTR
                                + dn * 8 + (q4 >> 1) * 8) * 2);
                uint32_t bv[4];
                ldsm_x4_t(bv, addr);
                mma_f16(oacc[dn],     pfrag, bv[0], bv[1]);
                mma_f16(oacc[dn + 1], pfrag, bv[2], bv[3]);
            }
        }

        int row0 = bmrow + gid, row1 = bmrow + 8 + gid;
        #pragma unroll
        for (int dn = 0; dn < 12; dn++) {
            int d = dn * 8 + 2 * tig;
            if (row0 < Nseq)
                *(__half2*)&CTX[(size_t)(b * Nseq + row0) * Dm + h * HD + d] =
                    __floats2half2_rn(oacc[dn][0] * inv0, oacc[dn][1] * inv0);
            if (row1 < Nseq)
                *(__half2*)&CTX[(size_t)(b * Nseq + row1) * Dm + h * HD + d] =
                    __floats2half2_rn(oacc[dn][2] * inv1, oacc[dn][3] * inv1);
        }
    }
}

// ---------------- adapter A (fp16 in): so8 + LN_a + residual + fused LN2 -> fp16 ----
__global__ __launch_bounds__(256) void so8ln_a_kernel(
    const __half* __restrict__ XPh, const __half* __restrict__ Ph, const float* __restrict__ xin,
    const float* __restrict__ eps, const float* __restrict__ scale_p,
    const float* __restrict__ g1, const float* __restrict__ b1,
    const float* __restrict__ g2, const float* __restrict__ b2,
    float* __restrict__ XRES, __half* __restrict__ X2h, float* __restrict__ err)
{
    __shared__ float y[Dm];
    __shared__ float errsum[8];
    __shared__ float sh0[8], sh1[8];
    size_t row = blockIdx.x;
    int tid = threadIdx.x;
    const int hd = Dm / 8;
    if (tid < 8) errsum[tid] = 0.f;
    __syncthreads();
    float scale = scale_p[0];
    const __half* xp = XPh + row * (size_t)Dm;
    const __half* bs = Ph + row * (size_t)Dm;

    float s = 0.f, s2 = 0.f;
    for (int i = tid; i < Dm; i += 256) {
        int head = i / hd;
        int pos = i - head * hd;
        float v;
        if (pos < 8) {
            int pr = pos >> 1;
            float ang = eps[row * 32 + head * 4 + pr] * scale;
            float sn, c;
            sincosf(ang, &sn, &c);
            float e = __half2float(xp[head * hd + 2 * pr]);
            float o = __half2float(xp[head * hd + 2 * pr + 1]);
            float rot, orig;
            if (pos & 1) { rot = e * sn + o * c; orig = o; }
            else         { rot = e * c - o * sn; orig = e; }
            float d = rot - orig;
            atomicAdd(&errsum[head], d * d);
            v = rot;
        } else v = __half2float(xp[i]);
        v += __half2float(bs[i]);
        y[i] = v;
        s += v; s2 += v * v;
    }
    s = warp_sum(s); s2 = warp_sum(s2);
    int w = tid >> 5, lane = tid & 31;
    if (lane == 0) { sh0[w] = s; sh1[w] = s2; }
    __syncthreads();
    float ts = 0.f, ts2 = 0.f;
    #pragma unroll
    for (int i = 0; i < 8; i++) { ts += sh0[i]; ts2 += sh1[i]; }
    if (tid == 0) {
        float e = 0.f;
        #pragma unroll
        for (int hh = 0; hh < 8; hh++) e += sqrtf(errsum[hh]);
        err[row] = e * 0.125f;
    }
    const float invD = 1.0f / (float)Dm;
    float mean = ts * invD;
    float rstd = rsqrtf(ts2 * invD - mean * mean + LN_EPS);
    __syncthreads();

    s = 0.f; s2 = 0.f;
    for (int i = tid; i < Dm; i += 256) {
        float v = (y[i] - mean) * rstd * g1[i] + b1[i] + __half2float(bs[i])
                  + xin[row * (size_t)Dm + i];
        XRES[row * (size_t)Dm + i] = v;
        y[i] = v;
        s += v; s2 += v * v;
    }
    s = warp_sum(s); s2 = warp_sum(s2);
    if (lane == 0) { sh0[w] = s; sh1[w] = s2; }
    __syncthreads();
    ts = 0.f; ts2 = 0.f;
    #pragma unroll
    for (int i = 0; i < 8; i++) { ts += sh0[i]; ts2 += sh1[i]; }
    float mean2 = ts * invD;
    float rstd2 = rsqrtf(ts2 * invD - mean2 * mean2 + LN_EPS);
    for (int i = tid; i < Dm; i += 256)
        X2h[row * (size_t)Dm + i] = __float2half((y[i] - mean2) * rstd2 * g2[i] + b2[i]);
}

// ---------------- adapter M (512 thr): so8 + LN_m + residual -> fp16 ; err tail ----
#define SOM_THREADS 512
__global__ __launch_bounds__(SOM_THREADS) void so8ln_m_kernel(
    const __half* __restrict__ H2h, const __half* __restrict__ H1h,
    const float* __restrict__ eps, const float* __restrict__ scale_p,
    const float* __restrict__ gg, const float* __restrict__ bb,
    const float* __restrict__ e1, float* __restrict__ out_tail,
    __half* __restrict__ H3h)
{
    __shared__ float y[HIDm];
    __shared__ float errsum[8];
    __shared__ float sh0[16], sh1[16];
    size_t row = blockIdx.x;
    int tid = threadIdx.x;
    const int hd = HIDm / 8;
    if (tid < 8) errsum[tid] = 0.f;
    __syncthreads();
    float scale = scale_p[0];
    const __half* xph = H2h + row * (size_t)HIDm;
    const __half* bsh = H1h + row * (size_t)HIDm;

    float s = 0.f, s2 = 0.f;
    for (int i = tid; i < HIDm; i += SOM_THREADS) {
        int head = i / hd;
        int pos = i - head * hd;
        float v;
        if (pos < 8) {
            int pr = pos >> 1;
            float ang = eps[row * 32 + head * 4 + pr] * scale;
            float sn, c;
            sincosf(ang, &sn, &c);
            float e = __half2float(xph[head * hd + 2 * pr]);
            float o = __half2float(xph[head * hd + 2 * pr + 1]);
            float rot, orig;
            if (pos & 1) { rot = e * sn + o * c; orig = o; }
            else         { rot = e * c - o * sn; orig = e; }
            float d = rot - orig;
            atomicAdd(&errsum[head], d * d);
            v = rot;
        } else v = __half2float(xph[i]);
        v += __half2float(bsh[i]);
        y[i] = v;
        s += v; s2 += v * v;
    }
    s = warp_sum(s); s2 = warp_sum(s2);
    int w = tid >> 5, lane = tid & 31;
    if (lane == 0) { sh0[w] = s; sh1[w] = s2; }
    __syncthreads();
    float ts = 0.f, ts2 = 0.f;
    #pragma unroll
    for (int i = 0; i < 16; i++) { ts += sh0[i]; ts2 += sh1[i]; }
    if (tid == 0) {
        float e = 0.f;
        #pragma unroll
        for (int hh = 0; hh < 8; hh++) e += sqrtf(errsum[hh]);
        out_tail[row] = e * 0.125f + e1[row];
    }
    const float invD = 1.0f / (float)HIDm;
    float mean = ts * invD;
    float rstd = rsqrtf(ts2 * invD - mean * mean + LN_EPS);
    for (int i = tid; i < HIDm; i += SOM_THREADS)
        H3h[row * (size_t)HIDm + i] =
            __float2half((y[i] - mean) * rstd * gg[i] + bb[i] + __half2float(bsh[i]));
}

// ---------------- launch ----------------
extern "C" void kernel_launch(void* const* d_in, const int* in_sizes, int n_in,
                              void* d_out, int out_size)
{
    const float* x       = (const float*)d_in[0];
    const float* qkv_w   = (const float*)d_in[1];
    const float* qkv_b   = (const float*)d_in[2];
    const float* proj_w  = (const float*)d_in[3];
    const float* proj_b  = (const float*)d_in[4];
    const float* norm1_g = (const float*)d_in[5];
    const float* norm1_b = (const float*)d_in[6];
    const float* norm2_g = (const float*)d_in[7];
    const float* norm2_b = (const float*)d_in[8];
    const float* orth_w_a = (const float*)d_in[9];
    const float* orth_b_a = (const float*)d_in[10];
    const float* scale_a  = (const float*)d_in[11];
    const float* ln_g_a   = (const float*)d_in[12];
    const float* ln_b_a   = (const float*)d_in[13];
    const float* orth_w_m = (const float*)d_in[14];
    const float* orth_b_m = (const float*)d_in[15];
    const float* scale_m  = (const float*)d_in[16];
    const float* ln_g_m   = (const float*)d_in[17];
    const float* ln_b_m   = (const float*)d_in[18];
    const float* fc1_w    = (const float*)d_in[19];
    const float* fc1_b    = (const float*)d_in[20];
    const float* fc2_w    = (const float*)d_in[21];
    const float* fc2_b    = (const float*)d_in[22];
    const float* eps_a    = (const float*)d_in[23];
    const float* eps_m    = (const float*)d_in[24];
    float* out = (float*)d_out;

    float *XRES, *E1;
    __half *X1h, *QKVh, *CTXh, *Ph, *X2h, *H1h, *H2h, *H3h;
    __half *WQKVh, *WPROJh, *WOAh, *WOMh, *WF1h, *WF2h;
    cudaGetSymbolAddress((void**)&XRES, g_XRES);
    cudaGetSymbolAddress((void**)&E1,   g_E1);
    cudaGetSymbolAddress((void**)&X1h,  g_X1h);
    cudaGetSymbolAddress((void**)&QKVh, g_QKVh);
    cudaGetSymbolAddress((void**)&CTXh, g_CTXh);
    cudaGetSymbolAddress((void**)&Ph,   g_Ph);
    cudaGetSymbolAddress((void**)&X2h,  g_X2h);
    cudaGetSymbolAddress((void**)&H1h,  g_H1h);
    cudaGetSymbolAddress((void**)&H2h,  g_H2h);
    cudaGetSymbolAddress((void**)&H3h,  g_H3h);
    cudaGetSymbolAddress((void**)&WQKVh,  g_WQKVh);
    cudaGetSymbolAddress((void**)&WPROJh, g_WPROJh);
    cudaGetSymbolAddress((void**)&WOAh,   g_WOAh);
    cudaGetSymbolAddress((void**)&WOMh,   g_WOMh);
    cudaGetSymbolAddress((void**)&WF1h,   g_WF1h);
    cudaGetSymbolAddress((void**)&WF2h,   g_WF2h);

    cudaFuncSetAttribute(attn_kernel, cudaFuncAttributeMaxDynamicSharedMemorySize, ATTN_SMEM);
    cudaFuncSetAttribute(gemm_tc, cudaFuncAttributeMaxDynamicSharedMemorySize, GEMM_SMEM_BYTES);

    const int MROWS = BNROWS;
    const int GY = (MROWS + 127) / 128;    // 99
    dim3 blk256(256);
    dim3 blk128(128);

    // 1) merged fp16 weight prepass
    prep_all<<<(CUM5 / 4 + 255) / 256, blk256>>>(qkv_w, proj_w, orth_w_a, orth_w_m, fc1_w, fc2_w);
    // 2) x1h = fp16(LN1(x))
    ln16_kernel<<<MROWS, blk256>>>(x, norm1_g, norm1_b, X1h, Dm);
    // 3) qkvh = x1 @ qkv_w^T + qkv_b
    gemm_tc<<<dim3(3 * Dm / 128, GY), blk128, GEMM_SMEM_BYTES>>>(
        X1h, WQKVh, qkv_b, nullptr, QKVh, nullptr, MROWS, 3 * Dm, Dm, 0);
    // 4) attention (mma) -> ctxh
    attn_kernel<<<Bsz * NHd, blk256, ATTN_SMEM>>>(QKVh, CTXh);
    // 5) proj -> Ph (fp16 only)
    gemm_tc<<<dim3(Dm / 128, GY), blk128, GEMM_SMEM_BYTES>>>(
        CTXh, WPROJh, proj_b, nullptr, Ph, nullptr, MROWS, Dm, Dm, 0);
    // 6) xp = P @ orth_w_a^T + b -> X1h (fp16, buffer reuse; X1h dead after step 3)
    gemm_tc<<<dim3(Dm / 128, GY), blk128, GEMM_SMEM_BYTES>>>(
        Ph, WOAh, orth_b_a, nullptr, X1h, nullptr, MROWS, Dm, Dm, 0);
    // 7) adapter A fused: xres (fp32) + x2h (fp16) + err1
    so8ln_a_kernel<<<MROWS, blk256>>>(X1h, Ph, x, eps_a, scale_a,
                                      ln_g_a, ln_b_a, norm2_g, norm2_b, XRES, X2h, E1);
    // 8) h1 = gelu(x2 @ fc1^T + b) -> H1h
    gemm_tc<<<dim3(HIDm / 128, GY), blk128, GEMM_SMEM_BYTES>>>(
        X2h, WF1h, fc1_b, nullptr, H1h, nullptr, MROWS, HIDm, Dm, 1);
    // 9) h2 = h1 @ orth_w_m^T + b -> H2h (fp16)
    gemm_tc<<<dim3(HIDm / 128, GY), blk128, GEMM_SMEM_BYTES>>>(
        H1h, WOMh, orth_b_m, nullptr, H2h, nullptr, MROWS, HIDm, HIDm, 0);
    // 10) adapter M fused (512 thr)
    so8ln_m_kernel<<<MROWS, SOM_THREADS>>>(H2h, H1h, eps_m, scale_m, ln_g_m, ln_b_m,
                                           E1, out + (size_t)MROWS * Dm, H3h);
    // 11) out = h3 @ fc2^T + b + xres
    gemm_tc<<<dim3(Dm / 128, GY), blk128, GEMM_SMEM_BYTES>>>(
        H3h, WF2h, fc2_b, out, nullptr, XRES, MROWS, Dm, HIDm, 0);
}